// round 4
// baseline (speedup 1.0000x reference)
#include <cuda_runtime.h>

// GaussianBlur2D: depthwise 11x11 Gaussian blur, reflect padding.
// x: (16, 64, 512, 512) fp32, sigma: (1,) fp32.
//
// Separable, horizontal-first via WARP SHUFFLES — zero smem, zero barriers:
//   - each thread loads ONE aligned float4 per row (DRAM-optimal stream)
//   - 14-col horizontal window assembled with 10 SHFLs; warp-edge lanes patch
//     their out-of-warp taps with predicated scalar loads (L1/L2 hits)
//   - 14-deep register window of h-blurred rows; vertical 11-tap in registers
// g2d[i][j] = (h[i]/S)*(h[j]/S) with S = sum(h)  == reference's 2D kernel.

#define KS    11
#define IMG   512
#define NT    128      // threads per block; NT*4 == IMG (one full row per block)
#define RPT   4        // output rows per loop iteration
#define STRIP 128      // output rows per block
#define FULL  0xffffffffu

__device__ __forceinline__ int refl(int i) {
    i = (i < 0) ? -i : i;
    return (i >= IMG) ? (2 * IMG - 2 - i) : i;
}

// Horizontal 11-tap blur for columns x..x+3 of one row.
// One aligned float4 load; neighbors gathered via warp shuffles.
__device__ __forceinline__ float4 hblur_row(const float* __restrict__ row,
                                            int x, int lane,
                                            const float* __restrict__ w) {
    const float4 q = *(const float4*)(row + x);

    float v[14];
    v[5] = q.x; v[6] = q.y; v[7] = q.z; v[8] = q.w;

    // from lane-1 (cols x-4..x-1) and lane-2 (col x-5)
    v[1] = __shfl_up_sync(FULL, q.x, 1);
    v[2] = __shfl_up_sync(FULL, q.y, 1);
    v[3] = __shfl_up_sync(FULL, q.z, 1);
    v[4] = __shfl_up_sync(FULL, q.w, 1);
    v[0] = __shfl_up_sync(FULL, q.w, 2);
    // from lane+1 (cols x+4..x+7) and lane+2 (col x+8)
    v[9]  = __shfl_down_sync(FULL, q.x, 1);
    v[10] = __shfl_down_sync(FULL, q.y, 1);
    v[11] = __shfl_down_sync(FULL, q.z, 1);
    v[12] = __shfl_down_sync(FULL, q.w, 1);
    v[13] = __shfl_down_sync(FULL, q.x, 2);

    // Patch warp-edge lanes from memory (reflect-safe; L1/L2 hits).
    if (lane == 0) {
        v[0] = row[refl(x - 5)];
        v[1] = row[refl(x - 4)];
        v[2] = row[refl(x - 3)];
        v[3] = row[refl(x - 2)];
        v[4] = row[refl(x - 1)];
    } else if (lane == 1) {
        v[0] = row[refl(x - 5)];
    }
    if (lane == 31) {
        v[9]  = row[refl(x + 4)];
        v[10] = row[refl(x + 5)];
        v[11] = row[refl(x + 6)];
        v[12] = row[refl(x + 7)];
        v[13] = row[refl(x + 8)];
    } else if (lane == 30) {
        v[13] = row[refl(x + 8)];
    }

    float o0 = 0.f, o1 = 0.f, o2 = 0.f, o3 = 0.f;
    #pragma unroll
    for (int j = 0; j < KS; j++) {
        const float wj = w[j];
        o0 = fmaf(wj, v[j],     o0);
        o1 = fmaf(wj, v[j + 1], o1);
        o2 = fmaf(wj, v[j + 2], o2);
        o3 = fmaf(wj, v[j + 3], o3);
    }
    return make_float4(o0, o1, o2, o3);
}

__global__ __launch_bounds__(NT, 4)
void gaussian_blur_kernel(const float* __restrict__ in, float* __restrict__ out,
                          const float* __restrict__ sigma) {
    const int t    = threadIdx.x;
    const int lane = t & 31;
    const int x    = t << 2;                    // this thread owns columns x..x+3
    const int plane = blockIdx.x >> 2;
    const int y0 = (blockIdx.x & 3) * STRIP;
    const float* __restrict__ img  = in  + (size_t)plane * (IMG * IMG);
    float*       __restrict__ oimg = out + (size_t)plane * (IMG * IMG);

    // Compute normalized 1D weights locally (cheap; removes prologue kernel).
    float w[KS];
    {
        float s = fabsf(sigma[0]) + 1e-6f;
        float inv = 1.0f / (2.0f * s * s);
        float sum = 0.0f;
        #pragma unroll
        for (int j = 0; j < KS; j++) {
            float r = (float)j - (float)(KS - 1) * 0.5f;
            w[j] = __expf(-r * r * inv);
            sum += w[j];
        }
        float rs = 1.0f / sum;
        #pragma unroll
        for (int j = 0; j < KS; j++) w[j] *= rs;
    }

    // win[k] = hblur of input row (ybase + k - 5), k = 0..13
    float4 win[14];
    #pragma unroll
    for (int k = 0; k < 14; k++)
        win[k] = hblur_row(img + (size_t)refl(y0 + k - 5) * IMG, x, lane, w);

    for (int yb = 0; yb < STRIP; yb += RPT) {
        const int y = y0 + yb;

        // Fetch + h-blur the next RPT rows (y+9 .. y+12); overlaps vblur FMAs.
        float4 nw[RPT];
        #pragma unroll
        for (int r = 0; r < RPT; r++)
            nw[r] = hblur_row(img + (size_t)refl(y + 9 + r) * IMG, x, lane, w);

        // Vertical 11-tap from the register window -> 4 output rows.
        #pragma unroll
        for (int r = 0; r < RPT; r++) {
            float ax = 0.f, ay = 0.f, az = 0.f, aw = 0.f;
            #pragma unroll
            for (int i = 0; i < KS; i++) {
                const float  wi = w[i];
                const float4 v  = win[r + i];
                ax = fmaf(wi, v.x, ax);
                ay = fmaf(wi, v.y, ay);
                az = fmaf(wi, v.z, az);
                aw = fmaf(wi, v.w, aw);
            }
            *(float4*)(oimg + (size_t)(y + r) * IMG + x) = make_float4(ax, ay, az, aw);
        }

        // Slide the window down by RPT rows.
        #pragma unroll
        for (int k = 0; k < 14 - RPT; k++) win[k] = win[k + RPT];
        #pragma unroll
        for (int r = 0; r < RPT; r++)      win[10 + r] = nw[r];
    }
}

extern "C" void kernel_launch(void* const* d_in, const int* in_sizes, int n_in,
                              void* d_out, int out_size) {
    const float* x     = (const float*)d_in[0];
    const float* sigma = (const float*)d_in[1];
    float*       out   = (float*)d_out;

    const int n_img = in_sizes[0] / (IMG * IMG);   // B*C planes

    const int strips = IMG / STRIP;                // 4
    gaussian_blur_kernel<<<n_img * strips, NT>>>(x, out, sigma);
}

// round 5
// speedup vs baseline: 2.2503x; 2.2503x over previous
#include <cuda_runtime.h>

// GaussianBlur2D: depthwise 11x11 Gaussian blur, reflect padding.
// x: (16, 64, 512, 512) fp32, sigma: (1,) fp32.
//
// Separable, vertical-first (raw-row register window), horizontal via smem
// with minimal traffic:
//   - vertical 11-tap entirely in registers (14-row sliding float4 window)
//   - vblur row stored with ONE STS.128; own quad reused from registers
//   - horizontal window = own regs + 2x LDS.128 (neighbor quads) + 2 SHFLs
//     (end taps from lane+-2), edge lanes patch from smem halo
//   - double-buffered smem row -> ONE __syncthreads() per 4 output rows
// g2d[i][j] = (h[i]/S)*(h[j]/S) with S = sum(h)  == reference's 2D kernel.

#define KS    11
#define IMG   512
#define NT    128      // threads per block; NT*4 == IMG
#define RPT   4        // output rows per loop iteration
#define STRIP 128      // output rows per block
#define HB    8        // smem halo floats on each side
#define SVW   (HB + IMG + HB)   // 528
#define FULL  0xffffffffu

__device__ __forceinline__ int refl(int i) {
    i = (i < 0) ? -i : i;
    return (i >= IMG) ? (2 * IMG - 2 - i) : i;
}

__global__ __launch_bounds__(NT, 4)
void gaussian_blur_kernel(const float* __restrict__ in, float* __restrict__ out,
                          const float* __restrict__ sigma) {
    // double-buffered vblur rows, with mirrored halo so all horiz reads are in-bounds
    __shared__ float s_v[2][RPT][SVW];

    const int t    = threadIdx.x;
    const int lane = t & 31;
    const int x    = t << 2;                    // this thread owns columns x..x+3
    const int plane = blockIdx.x >> 2;
    const int y0 = (blockIdx.x & 3) * STRIP;
    const float* __restrict__ img  = in  + (size_t)plane * (IMG * IMG);
    float*       __restrict__ oimg = out + (size_t)plane * (IMG * IMG);

    // normalized 1D weights (computed locally; no prologue kernel)
    float w[KS];
    {
        float s = fabsf(sigma[0]) + 1e-6f;
        float inv = 1.0f / (2.0f * s * s);
        float sum = 0.0f;
        #pragma unroll
        for (int j = 0; j < KS; j++) {
            float r = (float)j - (float)(KS - 1) * 0.5f;
            w[j] = __expf(-r * r * inv);
            sum += w[j];
        }
        float rs = 1.0f / sum;
        #pragma unroll
        for (int j = 0; j < KS; j++) w[j] *= rs;
    }

    // win[k] = raw input row (y0 + k - 5), k = 0..13
    float4 win[14];
    #pragma unroll
    for (int k = 0; k < 14; k++)
        win[k] = *(const float4*)(img + (size_t)refl(y0 + k - 5) * IMG + x);

    int buf = 0;
    for (int yb = 0; yb < STRIP; yb += RPT, buf ^= 1) {
        const int y = y0 + yb;

        // Prefetch next RPT raw rows (long-latency; overlaps all math below).
        float4 pre[RPT];
        #pragma unroll
        for (int r = 0; r < RPT; r++)
            pre[r] = *(const float4*)(img + (size_t)refl(y + 9 + r) * IMG + x);

        // ---- vertical 11-tap (registers only) ----
        float4 va[RPT];
        #pragma unroll
        for (int r = 0; r < RPT; r++) {
            float ax = 0.f, ay = 0.f, az = 0.f, aw = 0.f;
            #pragma unroll
            for (int i = 0; i < KS; i++) {
                const float  wi = w[i];
                const float4 v  = win[r + i];
                ax = fmaf(wi, v.x, ax);
                ay = fmaf(wi, v.y, ay);
                az = fmaf(wi, v.z, az);
                aw = fmaf(wi, v.w, aw);
            }
            va[r] = make_float4(ax, ay, az, aw);

            // one vectorized store of own quad
            *(float4*)&s_v[buf][r][HB + x] = va[r];

            // mirrored halo: col -c <- col c (c=1..8), col 512+k <- col 510-k (k=0..7)
            const float av[4] = {ax, ay, az, aw};
            #pragma unroll
            for (int c = 0; c < 4; c++) {
                const int xc = x + c;
                if (xc >= 1 && xc <= HB)              s_v[buf][r][HB - xc]        = av[c];
                if (xc >= IMG - 2 - (HB - 1) && xc <= IMG - 2)
                                                      s_v[buf][r][HB + 1022 - xc] = av[c];
            }
        }
        __syncthreads();   // single barrier per iteration (double buffering)

        // ---- horizontal 11-tap: own regs + 2 LDS.128 + 2 SHFLs ----
        #pragma unroll
        for (int r = 0; r < RPT; r++) {
            const float4 q = va[r];                              // cols x..x+3
            const float4 L = *(const float4*)&s_v[buf][r][HB + x - 4]; // x-4..x-1
            const float4 R = *(const float4*)&s_v[buf][r][HB + x + 4]; // x+4..x+7

            float v0  = __shfl_up_sync  (FULL, q.w, 2);          // col x-5 from lane-2
            float v13 = __shfl_down_sync(FULL, q.x, 2);          // col x+8 from lane+2
            if (lane < 2)   v0  = s_v[buf][r][HB + x - 5];
            if (lane >= 30) v13 = s_v[buf][r][HB + x + 8];

            const float v[14] = {v0, L.x, L.y, L.z, L.w,
                                 q.x, q.y, q.z, q.w,
                                 R.x, R.y, R.z, R.w, v13};

            float o0 = 0.f, o1 = 0.f, o2 = 0.f, o3 = 0.f;
            #pragma unroll
            for (int j = 0; j < KS; j++) {
                const float wj = w[j];
                o0 = fmaf(wj, v[j],     o0);
                o1 = fmaf(wj, v[j + 1], o1);
                o2 = fmaf(wj, v[j + 2], o2);
                o3 = fmaf(wj, v[j + 3], o3);
            }
            *(float4*)(oimg + (size_t)(y + r) * IMG + x) = make_float4(o0, o1, o2, o3);
        }

        // ---- slide the window down by RPT rows ----
        #pragma unroll
        for (int k = 0; k < 14 - RPT; k++) win[k] = win[k + RPT];
        #pragma unroll
        for (int r = 0; r < RPT; r++)      win[10 + r] = pre[r];
    }
}

extern "C" void kernel_launch(void* const* d_in, const int* in_sizes, int n_in,
                              void* d_out, int out_size) {
    const float* x     = (const float*)d_in[0];
    const float* sigma = (const float*)d_in[1];
    float*       out   = (float*)d_out;

    const int n_img = in_sizes[0] / (IMG * IMG);   // B*C planes

    const int strips = IMG / STRIP;                // 4
    gaussian_blur_kernel<<<n_img * strips, NT>>>(x, out, sigma);
}